// round 11
// baseline (speedup 1.0000x reference)
#include <cuda_runtime.h>
#include <cstdint>

#define T_STEPS 128
#define BATCH   64
#define VDIM    2048
#define HDIM    1024
#define GDIM    4096   // 4*H

#define NCTA    128    // persistent CTAs (one per 8 hidden units)
#define NRECT   512    // 16 recurrence warps
#define NTHR    640    // + 4 gates-producer warps

// ---------------- scratch (static device globals; no allocation) ----------
__device__ float g_gates[(size_t)T_STEPS * BATCH * GDIM];  // 134 MB: x@Wi + b
__device__ float g_h[2][BATCH * HDIM];
__device__ float g_c[2][BATCH * HDIM];
__device__ int   g_eos[2][BATCH];
__device__ unsigned g_bar_count;
__device__ volatile unsigned g_bar_gen;
__device__ unsigned g_tiles_done[NCTA];   // per-CTA gates-tile counter

// ---------------- helpers ------------------------------------------------
__device__ __forceinline__ uint32_t f2tf32(float f) {
    uint32_t r;
    asm("cvt.rna.tf32.f32 %0, %1;" : "=r"(r) : "f"(f));
    return r;
}

__device__ __forceinline__ void st_tf32_4(uint32_t* d, float4 v) {
    uint4 u;
    u.x = f2tf32(v.x); u.y = f2tf32(v.y); u.z = f2tf32(v.z); u.w = f2tf32(v.w);
    *(uint4*)d = u;
}

__device__ __forceinline__ void mma_tf32(float c[4],
                                         uint32_t a0, uint32_t a1, uint32_t a2, uint32_t a3,
                                         uint32_t b0, uint32_t b1) {
    asm volatile(
        "mma.sync.aligned.m16n8k8.row.col.f32.tf32.tf32.f32 "
        "{%0,%1,%2,%3}, {%4,%5,%6,%7}, {%8,%9}, {%0,%1,%2,%3};\n"
        : "+f"(c[0]), "+f"(c[1]), "+f"(c[2]), "+f"(c[3])
        : "r"(a0), "r"(a1), "r"(a2), "r"(a3), "r"(b0), "r"(b1));
}

__device__ __forceinline__ float sigf(float x) {
    return 1.0f / (1.0f + expf(-x));
}

__device__ __forceinline__ void cpa16(void* dst_smem, const void* src_glob) {
    uint32_t d = (uint32_t)__cvta_generic_to_shared(dst_smem);
    asm volatile("cp.async.cg.shared.global [%0], [%1], 16;\n" :: "r"(d), "l"(src_glob));
}
#define CP_COMMIT() asm volatile("cp.async.commit_group;\n" ::: "memory")
#define CP_WAIT1()  asm volatile("cp.async.wait_group 1;\n" ::: "memory")

__device__ __forceinline__ void pfL2(const void* p) {
    asm volatile("prefetch.global.L2 [%0];\n" :: "l"(p));
}

#define BAR_REC()  asm volatile("bar.sync 1, 512;\n" ::: "memory")
#define BAR_GEMM() asm volatile("bar.sync 2, 128;\n" ::: "memory")

// ---------------- init state ---------------------------------------------
__global__ void init_state(const float* __restrict__ c0,
                           const float* __restrict__ h0,
                           const unsigned char* __restrict__ eos0) {
    int i = blockIdx.x * blockDim.x + threadIdx.x;
    if (i < BATCH * HDIM) {
        g_c[0][i] = c0[i];
        g_h[0][i] = h0[i];
    }
    if (i < BATCH) g_eos[0][i] = eos0[i] ? 1 : 0;
    if (i < NCTA) g_tiles_done[i] = 0;
    if (i == 0) { g_bar_count = 0; g_bar_gen = 0; }
}

// ---------------- smem layout ----------------------------------------------
#define NSTG 3
#define WS_STR 36
#define HS_STR 36
#define GS_STR 34
#define GA_STR 20
#define GB_STR 36
#define WS_WORDS (HDIM * WS_STR)                // 36864
#define HS_WORDS (NSTG * BATCH * HS_STR)        // 6912
#define GS_WORDS (2 * BATCH * GS_STR)           // 4352
#define GA_WORDS (2 * 128 * GA_STR)             // 5120 (gemm A dbl)
#define GB_WORDS (2 * 16 * GB_STR)              // 1152 (gemm B dbl)
#define PSMEM_BYTES ((WS_WORDS + HS_WORDS + GS_WORDS + GA_WORDS + GB_WORDS) * 4) // 217600

#define N_TILES 64    // gates tiles per CTA (128 rows x 32 cols each)

__device__ __forceinline__ void grid_barrier() {
    BAR_REC();
    if (threadIdx.x == 0) {
        __threadfence();
        unsigned gen = g_bar_gen;
        unsigned t = atomicAdd(&g_bar_count, 1u);
        if (t == NCTA - 1) {
            g_bar_count = 0;
            __threadfence();
            g_bar_gen = gen + 1;
        } else {
            while (g_bar_gen == gen) { }
            __threadfence();
        }
    }
    BAR_REC();
}

// ---------------- fused persistent kernel ----------------------------------
__global__ __launch_bounds__(NTHR, 1) void lstm_fused(const float* __restrict__ X,
                                                      const float* __restrict__ Wi,
                                                      const float* __restrict__ Wh,
                                                      const float* __restrict__ bias,
                                                      float* __restrict__ ys) {
    extern __shared__ uint32_t dsm[];
    uint32_t* ws  = dsm;                                  // [1024][36]
    float*    hs  = (float*)(dsm + WS_WORDS);             // [3][64][36]
    float*    gsm = (float*)(dsm + WS_WORDS + HS_WORDS);  // [2][64][34]
    uint32_t* ga  = dsm + WS_WORDS + HS_WORDS + GS_WORDS; // gemm A dbl
    uint32_t* gb  = ga + GA_WORDS;                        // gemm B dbl

    const int tid  = threadIdx.x;
    const int lane = tid & 31;
    const int w    = tid >> 5;        // warp 0..19
    const int lq   = lane >> 2;
    const int lr   = lane & 3;
    const int j    = blockIdx.x;      // hidden slice

    if (w >= 16) {
        // ================= gates producer: 4 warps ======================
        // tile s: g_gates rows [s*128, s*128+128), this CTA's 32 columns.
        const int gtid = tid - NRECT;      // 0..127
        const int gw   = w - 16;           // 0..3
        const int wm   = gw * 32;          // warp M offset in tile

        const int ar   = gtid;             // A loader: row, 16 k (4 float4)
        const int brow = gtid >> 3;        // B loader: k-row 0..15
        const int bq   = (gtid & 7) * 4;   // local col quad 0,4..28
        const float* bsrc = Wi + (size_t)brow * GDIM + (bq >> 3) * HDIM + j * 8 + (bq & 7);

        for (int s = 0; s < N_TILES; s++) {
            const int m0 = s * 128;
            const float* asrc = X + (size_t)(m0 + ar) * VDIM;

            float acc[2][4][4];
#pragma unroll
            for (int mi = 0; mi < 2; mi++)
#pragma unroll
                for (int ni = 0; ni < 4; ni++)
#pragma unroll
                    for (int q = 0; q < 4; q++) acc[mi][ni][q] = 0.0f;

            float4 av[4], bv;
#pragma unroll
            for (int v = 0; v < 4; v++) av[v] = *(const float4*)(asrc + v * 4);
            bv = *(const float4*)(bsrc);

            const int NIT = VDIM / 16;     // 128
            for (int it = 0; it < NIT; it++) {
                const int p = it & 1;
                uint32_t* Ab = ga + p * (128 * GA_STR);
                uint32_t* Bb = gb + p * (16 * GB_STR);
#pragma unroll
                for (int v = 0; v < 4; v++)
                    st_tf32_4(Ab + ar * GA_STR + v * 4, av[v]);
                st_tf32_4(Bb + brow * GB_STR + bq, bv);
                BAR_GEMM();

                if (it + 1 < NIT) {
                    int k1 = (it + 1) * 16;
#pragma unroll
                    for (int v = 0; v < 4; v++)
                        av[v] = *(const float4*)(asrc + k1 + v * 4);
                    bv = *(const float4*)(bsrc + (size_t)k1 * GDIM);
                }

#pragma unroll
                for (int kk = 0; kk < 16; kk += 8) {
                    uint32_t afr[2][4];
#pragma unroll
                    for (int mi = 0; mi < 2; mi++) {
                        int r = wm + mi * 16 + lq;
                        afr[mi][0] = Ab[r * GA_STR + kk + lr];
                        afr[mi][1] = Ab[(r + 8) * GA_STR + kk + lr];
                        afr[mi][2] = Ab[r * GA_STR + kk + lr + 4];
                        afr[mi][3] = Ab[(r + 8) * GA_STR + kk + lr + 4];
                    }
#pragma unroll
                    for (int ni = 0; ni < 4; ni++) {
                        int c = ni * 8 + lq;
                        uint32_t b0 = Bb[(kk + lr) * GB_STR + c];
                        uint32_t b1 = Bb[(kk + lr + 4) * GB_STR + c];
#pragma unroll
                        for (int mi = 0; mi < 2; mi++)
                            mma_tf32(acc[mi][ni], afr[mi][0], afr[mi][1],
                                     afr[mi][2], afr[mi][3], b0, b1);
                    }
                }
                // buffer reuse safe: tile-done BAR_GEMM below + per-iter BAR
            }

            // epilogue: write this CTA's 32 gate columns (+bias)
#pragma unroll
            for (int mi = 0; mi < 2; mi++) {
#pragma unroll
                for (int ni = 0; ni < 4; ni++) {
                    int r0   = m0 + wm + mi * 16 + lq;
                    int gcol = ni * HDIM + j * 8 + 2 * lr;
                    float bl = __ldg(bias + gcol);
                    float bh = __ldg(bias + gcol + 1);
                    g_gates[(size_t)r0 * GDIM + gcol]           = acc[mi][ni][0] + bl;
                    g_gates[(size_t)r0 * GDIM + gcol + 1]       = acc[mi][ni][1] + bh;
                    g_gates[(size_t)(r0 + 8) * GDIM + gcol]     = acc[mi][ni][2] + bl;
                    g_gates[(size_t)(r0 + 8) * GDIM + gcol + 1] = acc[mi][ni][3] + bh;
                }
            }

            __threadfence();
            BAR_GEMM();
            if (gtid == 0) atomicAdd(&g_tiles_done[j], 1u);
        }
        return;   // producers done; no further barriers involve them
    }

    // ================= recurrence: 16 warps (R10 logic) =====================
    const int kh   = w >> 3;               // k-half
    const int wm16 = ((w >> 1) & 3) * 16;  // M offset
    const int wn   = w & 1;                // gate pair

    // ---- preload Wh slice into SMEM once (converted to tf32) ----
    {
        const int rr = tid >> 3;
        const int q  = tid & 7;
        const int g  = q >> 1;
        const int half = q & 1;
        for (int base = 0; base < HDIM; base += 64) {
            float4 v = *(const float4*)(Wh + (size_t)(base + rr) * GDIM + g * HDIM + j * 8 + half * 4);
            st_tf32_4(ws + (base + rr) * WS_STR + q * 4, v);
        }
    }
    BAR_REC();

    const int hr = tid >> 3;
    const int hc = (tid & 7) * 4;
    const int NIT = HDIM / 32;
    const int er = tid >> 3;          // epilogue batch row
    const int eu = tid & 7;           // epilogue hidden unit

    for (int t = 0; t < T_STEPS; t++) {
        // ---- wait for this step's gates tile (tile t/2) ----
        if (tid == 0) {
            unsigned need = (unsigned)(t >> 1) + 1u;
            while (((volatile unsigned*)g_tiles_done)[j] < need) { }
        }
        BAR_REC();
        __threadfence();

        const int cur = t & 1;
        const int nxt = cur ^ 1;
        const float* hprev = g_h[cur];
        const float* cprev = g_c[cur];
        float* hnex = g_h[nxt];
        float* cnex = g_c[nxt];
        const float* gx = g_gates + (size_t)t * BATCH * GDIM;

        // ---- L2 prefetch of this step's epilogue gate operands ----
        {
            const float* gp = gx + (size_t)er * GDIM + j * 8 + eu;
            pfL2(gp);
            pfL2(gp + HDIM);
            pfL2(gp + 2 * HDIM);
            pfL2(gp + 3 * HDIM);
        }

        float acc[2][4];
#pragma unroll
        for (int ni = 0; ni < 2; ni++)
#pragma unroll
            for (int q = 0; q < 4; q++) acc[ni][q] = 0.0f;

        // ---- cp.async pipeline prologue ----
#pragma unroll
        for (int s = 0; s < 2; s++) {
            float* hb = hs + s * (BATCH * HS_STR);
            cpa16(hb + hr * HS_STR + hc, hprev + (size_t)hr * HDIM + s * 32 + hc);
            CP_COMMIT();
        }

        for (int it = 0; it < NIT; it++) {
            CP_WAIT1();
            BAR_REC();

            if (it + 2 < NIT) {
                float* hb2 = hs + ((it + 2) % NSTG) * (BATCH * HS_STR);
                cpa16(hb2 + hr * HS_STR + hc, hprev + (size_t)hr * HDIM + (it + 2) * 32 + hc);
            }
            CP_COMMIT();

            const float* hb = hs + (it % NSTG) * (BATCH * HS_STR);
            const int k0 = it * 32;
#pragma unroll
            for (int ks = 0; ks < 2; ks++) {
                const int kk = kh * 16 + ks * 8;
                int r = wm16 + lq;
                uint32_t a0 = f2tf32(hb[r * HS_STR + kk + lr]);
                uint32_t a1 = f2tf32(hb[(r + 8) * HS_STR + kk + lr]);
                uint32_t a2 = f2tf32(hb[r * HS_STR + kk + lr + 4]);
                uint32_t a3 = f2tf32(hb[(r + 8) * HS_STR + kk + lr + 4]);
#pragma unroll
                for (int ni = 0; ni < 2; ni++) {
                    int g = wn * 2 + ni;
                    uint32_t b0 = ws[(k0 + kk + lr) * WS_STR + g * 8 + lq];
                    uint32_t b1 = ws[(k0 + kk + lr + 4) * WS_STR + g * 8 + lq];
                    mma_tf32(acc[ni], a0, a1, a2, a3, b0, b1);
                }
            }
        }

        // ---- exchange: dump warp partials to gsm[kh][64][34] ----
        {
            float* gs = gsm + kh * (BATCH * GS_STR);
#pragma unroll
            for (int ni = 0; ni < 2; ni++) {
                int col = (wn * 2 + ni) * 8 + 2 * lr;
                int row = wm16 + lq;
                gs[row * GS_STR + col]           = acc[ni][0];
                gs[row * GS_STR + col + 1]       = acc[ni][1];
                gs[(row + 8) * GS_STR + col]     = acc[ni][2];
                gs[(row + 8) * GS_STR + col + 1] = acc[ni][3];
            }
        }
        BAR_REC();

        // ---- cell epilogue: one output per thread ----
        {
            const int r = er, u = eu;
            const int hcol = j * 8 + u;
            const float* g0 = gsm + r * GS_STR;
            const float* g1 = gsm + BATCH * GS_STR + r * GS_STR;

            bool m = (__ldcg(&g_eos[cur][r]) != 0);
            const float* gp = gx + (size_t)r * GDIM + hcol;
            float iv = g0[u]      + g1[u]      + __ldg(gp);
            float fv = g0[8 + u]  + g1[8 + u]  + __ldg(gp + HDIM);
            float gv = g0[16 + u] + g1[16 + u] + __ldg(gp + 2 * HDIM);
            float ov = g0[24 + u] + g1[24 + u] + __ldg(gp + 3 * HDIM);

            float cp  = __ldcg(cprev + (size_t)r * HDIM + hcol);
            float ncv = sigf(fv) * cp + sigf(iv) * tanhf(gv);
            float nhv = sigf(ov) * tanhf(ncv);

            ys[((size_t)t * BATCH + r) * HDIM + hcol] = nhv;   // unmasked
            cnex[(size_t)r * HDIM + hcol] = m ? cp : ncv;
            hnex[(size_t)r * HDIM + hcol] = m ? __ldcg(hprev + (size_t)r * HDIM + hcol) : nhv;
        }

        if (blockIdx.x == 0 && tid < BATCH) {
            float xe = __ldg(X + ((size_t)t * BATCH + tid) * VDIM + 1);
            int eo = __ldcg(&g_eos[cur][tid]);
            g_eos[nxt][tid] = (eo != 0 || xe != 0.0f) ? 1 : 0;
        }

        __threadfence();
        grid_barrier();
    }
}

// ---------------- launch ---------------------------------------------------
extern "C" void kernel_launch(void* const* d_in, const int* in_sizes, int n_in,
                              void* d_out, int out_size) {
    const float* x  = (const float*)d_in[0];
    const float* Wi = (const float*)d_in[1];
    const float* Wh = (const float*)d_in[2];
    const float* b  = (const float*)d_in[3];
    const float* c0 = (const float*)d_in[4];
    const float* h0 = (const float*)d_in[5];
    const unsigned char* eos0 = (const unsigned char*)d_in[6];
    float* ys = (float*)d_out;

    static bool attr_done = false;
    if (!attr_done) {
        cudaFuncSetAttribute(lstm_fused,
                             cudaFuncAttributeMaxDynamicSharedMemorySize, PSMEM_BYTES);
        attr_done = true;
    }

    init_state<<<(BATCH * HDIM + 255) / 256, 256>>>(c0, h0, eos0);
    lstm_fused<<<NCTA, NTHR, PSMEM_BYTES>>>(x, Wi, Wh, b, ys);
}

// round 12
// speedup vs baseline: 1.8282x; 1.8282x over previous
#include <cuda_runtime.h>
#include <cstdint>

#define T_STEPS 128
#define BATCH   64
#define VDIM    2048
#define HDIM    1024
#define GDIM    4096   // 4*H

#define NCTA    128    // persistent CTAs (one per 8 hidden units)
#define NRECT   512    // 16 recurrence warps
#define NTHR    640    // + 4 gates-producer warps

// ---------------- scratch (static device globals; no allocation) ----------
__device__ float g_gates[(size_t)T_STEPS * BATCH * GDIM];  // 134 MB: x@Wi + b
__device__ float g_h[2][BATCH * HDIM];
__device__ float g_c[2][BATCH * HDIM];
__device__ int   g_eos[2][BATCH];
__device__ unsigned g_bar_count;
__device__ volatile unsigned g_bar_gen;
__device__ unsigned g_ready[T_STEPS];   // per-timestep gates tiles done (to 64)

// ---------------- helpers ------------------------------------------------
__device__ __forceinline__ uint32_t f2tf32(float f) {
    uint32_t r;
    asm("cvt.rna.tf32.f32 %0, %1;" : "=r"(r) : "f"(f));
    return r;
}

__device__ __forceinline__ void st_tf32_4(uint32_t* d, float4 v) {
    uint4 u;
    u.x = f2tf32(v.x); u.y = f2tf32(v.y); u.z = f2tf32(v.z); u.w = f2tf32(v.w);
    *(uint4*)d = u;
}

__device__ __forceinline__ void mma_tf32(float c[4],
                                         uint32_t a0, uint32_t a1, uint32_t a2, uint32_t a3,
                                         uint32_t b0, uint32_t b1) {
    asm volatile(
        "mma.sync.aligned.m16n8k8.row.col.f32.tf32.tf32.f32 "
        "{%0,%1,%2,%3}, {%4,%5,%6,%7}, {%8,%9}, {%0,%1,%2,%3};\n"
        : "+f"(c[0]), "+f"(c[1]), "+f"(c[2]), "+f"(c[3])
        : "r"(a0), "r"(a1), "r"(a2), "r"(a3), "r"(b0), "r"(b1));
}

__device__ __forceinline__ float sigf(float x) {
    return 1.0f / (1.0f + expf(-x));
}

__device__ __forceinline__ void cpa16(void* dst_smem, const void* src_glob) {
    uint32_t d = (uint32_t)__cvta_generic_to_shared(dst_smem);
    asm volatile("cp.async.cg.shared.global [%0], [%1], 16;\n" :: "r"(d), "l"(src_glob));
}
#define CP_COMMIT() asm volatile("cp.async.commit_group;\n" ::: "memory")
#define CP_WAIT1()  asm volatile("cp.async.wait_group 1;\n" ::: "memory")
#define CP_WAIT0()  asm volatile("cp.async.wait_group 0;\n" ::: "memory")

__device__ __forceinline__ void pfL2(const void* p) {
    asm volatile("prefetch.global.L2 [%0];\n" :: "l"(p));
}

#define BAR_REC()  asm volatile("bar.sync 1, 512;\n" ::: "memory")
#define BAR_GEMM() asm volatile("bar.sync 2, 128;\n" ::: "memory")

// ---------------- init state ---------------------------------------------
__global__ void init_state(const float* __restrict__ c0,
                           const float* __restrict__ h0,
                           const unsigned char* __restrict__ eos0) {
    int i = blockIdx.x * blockDim.x + threadIdx.x;
    if (i < BATCH * HDIM) {
        g_c[0][i] = c0[i];
        g_h[0][i] = h0[i];
    }
    if (i < BATCH) g_eos[0][i] = eos0[i] ? 1 : 0;
    if (i < T_STEPS) g_ready[i] = 0;
    if (i == 0) { g_bar_count = 0; g_bar_gen = 0; }
}

// ---------------- smem layout ----------------------------------------------
#define NSTG 3
#define WS_STR 36
#define HS_STR 36
#define GS_STR 34
#define PA_STR 20
#define PB_STR 68
#define WS_WORDS (HDIM * WS_STR)                // 36864
#define HS_WORDS (NSTG * BATCH * HS_STR)        // 6912
#define GS_WORDS (2 * BATCH * GS_STR)           // 4352
#define PA_WORDS (NSTG * 64 * PA_STR)           // 3840
#define PB_WORDS (NSTG * 16 * PB_STR)           // 3264
#define PSMEM_BYTES ((WS_WORDS + HS_WORDS + GS_WORDS + PA_WORDS + PB_WORDS) * 4) // 220928

#define N_PTILES 64   // producer tiles per CTA (64 rows x 64 cols, K=2048)

__device__ __forceinline__ void grid_barrier() {
    BAR_REC();
    if (threadIdx.x == 0) {
        __threadfence();
        unsigned gen = g_bar_gen;
        unsigned t = atomicAdd(&g_bar_count, 1u);
        if (t == NCTA - 1) {
            g_bar_count = 0;
            __threadfence();
            g_bar_gen = gen + 1;
        } else {
            while (g_bar_gen == gen) { }
            __threadfence();
        }
    }
    BAR_REC();
}

// ---------------- fused persistent kernel ----------------------------------
__global__ __launch_bounds__(NTHR, 1) void lstm_fused(const float* __restrict__ X,
                                                      const float* __restrict__ Wi,
                                                      const float* __restrict__ Wh,
                                                      const float* __restrict__ bias,
                                                      float* __restrict__ ys) {
    extern __shared__ uint32_t dsm[];
    uint32_t* ws  = dsm;                                  // [1024][36] tf32
    float*    hs  = (float*)(dsm + WS_WORDS);             // [3][64][36]
    float*    gsm = (float*)(dsm + WS_WORDS + HS_WORDS);  // [2][64][34]
    float*    pa  = (float*)(dsm + WS_WORDS + HS_WORDS + GS_WORDS);      // [3][64][20]
    float*    pb  = pa + PA_WORDS;                        // [3][16][68]

    const int tid  = threadIdx.x;
    const int lane = tid & 31;
    const int w    = tid >> 5;        // warp 0..19
    const int lq   = lane >> 2;
    const int lr   = lane & 3;
    const int j    = blockIdx.x;      // hidden slice

    if (w >= 16) {
        // ================= gates producer: 4 warps, cp.async pipeline ======
        const int gtid = tid - NRECT;      // 0..127
        const int gw   = w - 16;           // 0..3
        const int wm   = gw * 16;          // warp M offset (16 rows of 64)

        const int par = gtid >> 1;         // A row 0..63
        const int pac = (gtid & 1) * 8;    // A k col 0 or 8
        const int pbr = gtid >> 3;         // B k row 0..15
        const int pbc = (gtid & 7) * 8;    // B col 0..56

        const int NITP = VDIM / 16;        // 128

        for (int rtile = 0; rtile < N_PTILES; rtile++) {
            const int T  = blockIdx.x + rtile * NCTA;   // 0..8191
            const int by = T >> 6;                      // timestep 0..127
            const int bx = T & 63;                      // n-tile 0..63
            const int m0 = by * 64;
            const int n0 = bx * 64;

            const float* asrc = X  + (size_t)(m0 + par) * VDIM + pac;
            const float* bsrc = Wi + (size_t)pbr * GDIM + n0 + pbc;

            float acc[8][4];
#pragma unroll
            for (int ni = 0; ni < 8; ni++)
#pragma unroll
                for (int q = 0; q < 4; q++) acc[ni][q] = 0.0f;

            // drain previous tile, ensure all producer warps done reading
            CP_WAIT0();
            BAR_GEMM();

            // prologue: stages 0,1
#pragma unroll
            for (int s = 0; s < 2; s++) {
                float* Ab = pa + s * (64 * PA_STR);
                float* Bb = pb + s * (16 * PB_STR);
                cpa16(Ab + par * PA_STR + pac,     asrc + s * 16);
                cpa16(Ab + par * PA_STR + pac + 4, asrc + s * 16 + 4);
                cpa16(Bb + pbr * PB_STR + pbc,     bsrc + (size_t)(s * 16) * GDIM);
                cpa16(Bb + pbr * PB_STR + pbc + 4, bsrc + (size_t)(s * 16) * GDIM + 4);
                CP_COMMIT();
            }

            for (int it = 0; it < NITP; it++) {
                CP_WAIT1();
                BAR_GEMM();

                if (it + 2 < NITP) {
                    const int s2 = (it + 2) % NSTG;
                    float* Ab2 = pa + s2 * (64 * PA_STR);
                    float* Bb2 = pb + s2 * (16 * PB_STR);
                    cpa16(Ab2 + par * PA_STR + pac,     asrc + (it + 2) * 16);
                    cpa16(Ab2 + par * PA_STR + pac + 4, asrc + (it + 2) * 16 + 4);
                    cpa16(Bb2 + pbr * PB_STR + pbc,     bsrc + (size_t)((it + 2) * 16) * GDIM);
                    cpa16(Bb2 + pbr * PB_STR + pbc + 4, bsrc + (size_t)((it + 2) * 16) * GDIM + 4);
                }
                CP_COMMIT();

                const float* Ab = pa + (it % NSTG) * (64 * PA_STR);
                const float* Bb = pb + (it % NSTG) * (16 * PB_STR);
#pragma unroll
                for (int kk = 0; kk < 16; kk += 8) {
                    uint32_t a0 = f2tf32(Ab[(wm + lq) * PA_STR + kk + lr]);
                    uint32_t a1 = f2tf32(Ab[(wm + 8 + lq) * PA_STR + kk + lr]);
                    uint32_t a2 = f2tf32(Ab[(wm + lq) * PA_STR + kk + lr + 4]);
                    uint32_t a3 = f2tf32(Ab[(wm + 8 + lq) * PA_STR + kk + lr + 4]);
#pragma unroll
                    for (int ni = 0; ni < 8; ni++) {
                        uint32_t b0 = f2tf32(Bb[(kk + lr) * PB_STR + ni * 8 + lq]);
                        uint32_t b1 = f2tf32(Bb[(kk + lr + 4) * PB_STR + ni * 8 + lq]);
                        mma_tf32(acc[ni], a0, a1, a2, a3, b0, b1);
                    }
                }
                // 3-stage: buffer (it+2)%3 written next iter was consumed at it-1
            }

            // epilogue: gates tile + bias
#pragma unroll
            for (int ni = 0; ni < 8; ni++) {
                int r0 = m0 + wm + lq;
                int c0 = n0 + ni * 8 + 2 * lr;
                float bl = __ldg(bias + c0);
                float bh = __ldg(bias + c0 + 1);
                g_gates[(size_t)r0 * GDIM + c0]           = acc[ni][0] + bl;
                g_gates[(size_t)r0 * GDIM + c0 + 1]       = acc[ni][1] + bh;
                g_gates[(size_t)(r0 + 8) * GDIM + c0]     = acc[ni][2] + bl;
                g_gates[(size_t)(r0 + 8) * GDIM + c0 + 1] = acc[ni][3] + bh;
            }

            __threadfence();
            BAR_GEMM();
            if (gtid == 0) atomicAdd(&g_ready[by], 1u);
        }
        return;   // producers exit; rec barriers (bar 1) don't involve them
    }

    // ================= recurrence: 16 warps (R10 logic, BAR_REC) ============
    const int kh   = w >> 3;               // k-half
    const int wm16 = ((w >> 1) & 3) * 16;  // M offset
    const int wn   = w & 1;                // gate pair

    // ---- preload Wh slice into SMEM once (converted to tf32) ----
    {
        const int rr = tid >> 3;
        const int q  = tid & 7;
        const int g  = q >> 1;
        const int half = q & 1;
        for (int base = 0; base < HDIM; base += 64) {
            float4 v = *(const float4*)(Wh + (size_t)(base + rr) * GDIM + g * HDIM + j * 8 + half * 4);
            st_tf32_4(ws + (base + rr) * WS_STR + q * 4, v);
        }
    }
    BAR_REC();

    const int hr = tid >> 3;
    const int hc = (tid & 7) * 4;
    const int NIT = HDIM / 32;
    const int er = tid >> 3;          // epilogue batch row
    const int eu = tid & 7;           // epilogue hidden unit

    for (int t = 0; t < T_STEPS; t++) {
        // ---- wait for this step's gates (64 n-tiles of timestep t) ----
        if (tid == 0) {
            while (((volatile unsigned*)g_ready)[t] < 64u) { }
        }
        BAR_REC();
        __threadfence();

        const int cur = t & 1;
        const int nxt = cur ^ 1;
        const float* hprev = g_h[cur];
        const float* cprev = g_c[cur];
        float* hnex = g_h[nxt];
        float* cnex = g_c[nxt];
        const float* gx = g_gates + (size_t)t * BATCH * GDIM;

        // ---- L2 prefetch of this step's epilogue gate operands ----
        {
            const float* gp = gx + (size_t)er * GDIM + j * 8 + eu;
            pfL2(gp);
            pfL2(gp + HDIM);
            pfL2(gp + 2 * HDIM);
            pfL2(gp + 3 * HDIM);
        }

        float acc[2][4];
#pragma unroll
        for (int ni = 0; ni < 2; ni++)
#pragma unroll
            for (int q = 0; q < 4; q++) acc[ni][q] = 0.0f;

        // ---- cp.async pipeline prologue ----
#pragma unroll
        for (int s = 0; s < 2; s++) {
            float* hb = hs + s * (BATCH * HS_STR);
            cpa16(hb + hr * HS_STR + hc, hprev + (size_t)hr * HDIM + s * 32 + hc);
            CP_COMMIT();
        }

        for (int it = 0; it < NIT; it++) {
            CP_WAIT1();
            BAR_REC();

            if (it + 2 < NIT) {
                float* hb2 = hs + ((it + 2) % NSTG) * (BATCH * HS_STR);
                cpa16(hb2 + hr * HS_STR + hc, hprev + (size_t)hr * HDIM + (it + 2) * 32 + hc);
            }
            CP_COMMIT();

            const float* hb = hs + (it % NSTG) * (BATCH * HS_STR);
            const int k0 = it * 32;
#pragma unroll
            for (int ks = 0; ks < 2; ks++) {
                const int kk = kh * 16 + ks * 8;
                int r = wm16 + lq;
                uint32_t a0 = f2tf32(hb[r * HS_STR + kk + lr]);
                uint32_t a1 = f2tf32(hb[(r + 8) * HS_STR + kk + lr]);
                uint32_t a2 = f2tf32(hb[r * HS_STR + kk + lr + 4]);
                uint32_t a3 = f2tf32(hb[(r + 8) * HS_STR + kk + lr + 4]);
#pragma unroll
                for (int ni = 0; ni < 2; ni++) {
                    int g = wn * 2 + ni;
                    uint32_t b0 = ws[(k0 + kk + lr) * WS_STR + g * 8 + lq];
                    uint32_t b1 = ws[(k0 + kk + lr + 4) * WS_STR + g * 8 + lq];
                    mma_tf32(acc[ni], a0, a1, a2, a3, b0, b1);
                }
            }
        }

        // ---- exchange: dump warp partials to gsm[kh][64][34] ----
        {
            float* gs = gsm + kh * (BATCH * GS_STR);
#pragma unroll
            for (int ni = 0; ni < 2; ni++) {
                int col = (wn * 2 + ni) * 8 + 2 * lr;
                int row = wm16 + lq;
                gs[row * GS_STR + col]           = acc[ni][0];
                gs[row * GS_STR + col + 1]       = acc[ni][1];
                gs[(row + 8) * GS_STR + col]     = acc[ni][2];
                gs[(row + 8) * GS_STR + col + 1] = acc[ni][3];
            }
        }
        BAR_REC();

        // ---- cell epilogue: one output per thread ----
        {
            const int r = er, u = eu;
            const int hcol = j * 8 + u;
            const float* g0 = gsm + r * GS_STR;
            const float* g1 = gsm + BATCH * GS_STR + r * GS_STR;

            bool m = (__ldcg(&g_eos[cur][r]) != 0);
            const float* gp = gx + (size_t)r * GDIM + hcol;
            float iv = g0[u]      + g1[u]      + __ldg(gp);
            float fv = g0[8 + u]  + g1[8 + u]  + __ldg(gp + HDIM);
            float gv = g0[16 + u] + g1[16 + u] + __ldg(gp + 2 * HDIM);
            float ov = g0[24 + u] + g1[24 + u] + __ldg(gp + 3 * HDIM);

            float cp  = __ldcg(cprev + (size_t)r * HDIM + hcol);
            float ncv = sigf(fv) * cp + sigf(iv) * tanhf(gv);
            float nhv = sigf(ov) * tanhf(ncv);

            ys[((size_t)t * BATCH + r) * HDIM + hcol] = nhv;   // unmasked
            cnex[(size_t)r * HDIM + hcol] = m ? cp : ncv;
            hnex[(size_t)r * HDIM + hcol] = m ? __ldcg(hprev + (size_t)r * HDIM + hcol) : nhv;
        }

        if (blockIdx.x == 0 && tid < BATCH) {
            float xe = __ldg(X + ((size_t)t * BATCH + tid) * VDIM + 1);
            int eo = __ldcg(&g_eos[cur][tid]);
            g_eos[nxt][tid] = (eo != 0 || xe != 0.0f) ? 1 : 0;
        }

        __threadfence();
        grid_barrier();
    }
}

// ---------------- launch ---------------------------------------------------
extern "C" void kernel_launch(void* const* d_in, const int* in_sizes, int n_in,
                              void* d_out, int out_size) {
    const float* x  = (const float*)d_in[0];
    const float* Wi = (const float*)d_in[1];
    const float* Wh = (const float*)d_in[2];
    const float* b  = (const float*)d_in[3];
    const float* c0 = (const float*)d_in[4];
    const float* h0 = (const float*)d_in[5];
    const unsigned char* eos0 = (const unsigned char*)d_in[6];
    float* ys = (float*)d_out;

    static bool attr_done = false;
    if (!attr_done) {
        cudaFuncSetAttribute(lstm_fused,
                             cudaFuncAttributeMaxDynamicSharedMemorySize, PSMEM_BYTES);
        attr_done = true;
    }

    init_state<<<(BATCH * HDIM + 255) / 256, 256>>>(c0, h0, eos0);
    lstm_fused<<<NCTA, NTHR, PSMEM_BYTES>>>(x, Wi, Wh, b, ys);
}

// round 14
// speedup vs baseline: 2.3857x; 1.3049x over previous
#include <cuda_runtime.h>
#include <cstdint>

#define T_STEPS 128
#define BATCH   64
#define VDIM    2048
#define HDIM    1024
#define GDIM    4096   // 4*H

#define NCTA    128    // persistent CTAs (one per 8 hidden units)
#define NTHR    512    // 16 warps: 4 (M) x 2 (N/gate-pair) x 2 (K-split)

// ---------------- scratch (static device globals; no allocation) ----------
__device__ float g_gates[(size_t)T_STEPS * BATCH * GDIM];  // 134 MB: x@Wi + b
__device__ float g_h[2][BATCH * HDIM];
__device__ float g_c[2][BATCH * HDIM];
__device__ int   g_eos[2][BATCH];
__device__ unsigned g_bar_count;
__device__ volatile unsigned g_bar_gen;

// ---------------- helpers ------------------------------------------------
__device__ __forceinline__ uint32_t f2tf32(float f) {
    uint32_t r;
    asm("cvt.rna.tf32.f32 %0, %1;" : "=r"(r) : "f"(f));
    return r;
}

__device__ __forceinline__ void st_tf32_4(uint32_t* d, float4 v) {
    uint4 u;
    u.x = f2tf32(v.x); u.y = f2tf32(v.y); u.z = f2tf32(v.z); u.w = f2tf32(v.w);
    *(uint4*)d = u;
}

__device__ __forceinline__ void mma_tf32(float c[4],
                                         uint32_t a0, uint32_t a1, uint32_t a2, uint32_t a3,
                                         uint32_t b0, uint32_t b1) {
    asm volatile(
        "mma.sync.aligned.m16n8k8.row.col.f32.tf32.tf32.f32 "
        "{%0,%1,%2,%3}, {%4,%5,%6,%7}, {%8,%9}, {%0,%1,%2,%3};\n"
        : "+f"(c[0]), "+f"(c[1]), "+f"(c[2]), "+f"(c[3])
        : "r"(a0), "r"(a1), "r"(a2), "r"(a3), "r"(b0), "r"(b1));
}

__device__ __forceinline__ float sigf(float x) {
    return 1.0f / (1.0f + expf(-x));
}

__device__ __forceinline__ void cpa16(void* dst_smem, const void* src_glob) {
    uint32_t d = (uint32_t)__cvta_generic_to_shared(dst_smem);
    asm volatile("cp.async.cg.shared.global [%0], [%1], 16;\n" :: "r"(d), "l"(src_glob));
}
#define CP_COMMIT() asm volatile("cp.async.commit_group;\n" ::: "memory")
#define CP_WAIT1()  asm volatile("cp.async.wait_group 1;\n" ::: "memory")

__device__ __forceinline__ void pfL2(const void* p) {
    asm volatile("prefetch.global.L2 [%0];\n" :: "l"(p));
}

// ---------------- init state ---------------------------------------------
__global__ void init_state(const float* __restrict__ c0,
                           const float* __restrict__ h0,
                           const unsigned char* __restrict__ eos0) {
    int i = blockIdx.x * blockDim.x + threadIdx.x;
    if (i < BATCH * HDIM) {
        g_c[0][i] = c0[i];
        g_h[0][i] = h0[i];
    }
    if (i < BATCH) g_eos[0][i] = eos0[i] ? 1 : 0;
    if (i == 0) { g_bar_count = 0; g_bar_gen = 0; }
}

// ---------------- phase 1: gates_x = X @ Wi + b  (round-4/10 proven) -------
#define G1_BM 128
#define G1_BN 128
#define G1_BK 16
#define G1_ASTR 20
#define G1_BSTR 132

__global__ __launch_bounds__(256) void gemm1(const float* __restrict__ X,
                                             const float* __restrict__ Wi,
                                             const float* __restrict__ bias) {
    __shared__ uint32_t As[2][G1_BM * G1_ASTR];
    __shared__ uint32_t Bs[2][G1_BK * G1_BSTR];

    const int tid  = threadIdx.x;
    const int lane = tid & 31;
    const int wid  = tid >> 5;
    const int wm   = (wid >> 1) * 32;
    const int wn   = (wid & 1) * 64;
    const int lq   = lane >> 2;
    const int lr   = lane & 3;

    const int m0 = blockIdx.y * G1_BM;
    const int n0 = blockIdx.x * G1_BN;

    float acc[2][8][4];
#pragma unroll
    for (int mi = 0; mi < 2; mi++)
#pragma unroll
        for (int ni = 0; ni < 8; ni++)
#pragma unroll
            for (int q = 0; q < 4; q++) acc[mi][ni][q] = 0.0f;

    const int ar = tid >> 1;
    const int ac = (tid & 1) * 8;
    const int br = tid >> 4;
    const int bc = (tid & 15) * 8;

    const float* asrc = X  + (size_t)(m0 + ar) * VDIM + ac;
    const float* bsrc = Wi + (size_t)br * GDIM + n0 + bc;

    float4 av0 = *(const float4*)(asrc);
    float4 av1 = *(const float4*)(asrc + 4);
    float4 bv0 = *(const float4*)(bsrc);
    float4 bv1 = *(const float4*)(bsrc + 4);

    const int NIT = VDIM / G1_BK;   // 128
    for (int it = 0; it < NIT; it++) {
        const int p = it & 1;
        st_tf32_4(&As[p][ar * G1_ASTR + ac],     av0);
        st_tf32_4(&As[p][ar * G1_ASTR + ac + 4], av1);
        st_tf32_4(&Bs[p][br * G1_BSTR + bc],     bv0);
        st_tf32_4(&Bs[p][br * G1_BSTR + bc + 4], bv1);
        __syncthreads();

        if (it + 1 < NIT) {
            int k1 = (it + 1) * G1_BK;
            av0 = *(const float4*)(asrc + k1);
            av1 = *(const float4*)(asrc + k1 + 4);
            bv0 = *(const float4*)(bsrc + (size_t)k1 * GDIM);
            bv1 = *(const float4*)(bsrc + (size_t)k1 * GDIM + 4);
        }

        const uint32_t* as = As[p];
        const uint32_t* bs = Bs[p];
#pragma unroll
        for (int kk = 0; kk < G1_BK; kk += 8) {
            uint32_t afr[2][4];
#pragma unroll
            for (int mi = 0; mi < 2; mi++) {
                int r = wm + mi * 16 + lq;
                afr[mi][0] = as[r * G1_ASTR + kk + lr];
                afr[mi][1] = as[(r + 8) * G1_ASTR + kk + lr];
                afr[mi][2] = as[r * G1_ASTR + kk + lr + 4];
                afr[mi][3] = as[(r + 8) * G1_ASTR + kk + lr + 4];
            }
            uint32_t bfr[8][2];
#pragma unroll
            for (int ni = 0; ni < 8; ni++) {
                int c = wn + ni * 8 + lq;
                bfr[ni][0] = bs[(kk + lr) * G1_BSTR + c];
                bfr[ni][1] = bs[(kk + lr + 4) * G1_BSTR + c];
            }
#pragma unroll
            for (int mi = 0; mi < 2; mi++)
#pragma unroll
                for (int ni = 0; ni < 8; ni++)
                    mma_tf32(acc[mi][ni], afr[mi][0], afr[mi][1], afr[mi][2], afr[mi][3],
                             bfr[ni][0], bfr[ni][1]);
        }
    }

#pragma unroll
    for (int mi = 0; mi < 2; mi++) {
#pragma unroll
        for (int ni = 0; ni < 8; ni++) {
            int r0 = m0 + wm + mi * 16 + lq;
            int c0 = n0 + wn + ni * 8 + 2 * lr;
            float bl = bias[c0];
            float bh = bias[c0 + 1];
            g_gates[(size_t)r0 * GDIM + c0]           = acc[mi][ni][0] + bl;
            g_gates[(size_t)r0 * GDIM + c0 + 1]       = acc[mi][ni][1] + bh;
            g_gates[(size_t)(r0 + 8) * GDIM + c0]     = acc[mi][ni][2] + bl;
            g_gates[(size_t)(r0 + 8) * GDIM + c0 + 1] = acc[mi][ni][3] + bh;
        }
    }
}

// ---------------- phase 2: persistent recurrent kernel ---------------------
// R10 logic with: 64-wide k-tiles (16 iters/step, half the barriers) and
// per-CTA staggered k-order (spreads the post-barrier L2 burst 16x).
#define NSTG 3
#define KTILE 64
#define NKT   (HDIM / KTILE)        // 16
#define WS_STR 36
#define HS_STR 68
#define GS_STR 34
#define WS_WORDS (HDIM * WS_STR)                // 36864
#define HS_WORDS (NSTG * BATCH * HS_STR)        // 13056
#define GS_WORDS (2 * BATCH * GS_STR)           // 4352
#define PSMEM_BYTES ((WS_WORDS + HS_WORDS + GS_WORDS) * 4) // 217088 B

__device__ __forceinline__ void grid_barrier() {
    __syncthreads();
    if (threadIdx.x == 0) {
        __threadfence();
        unsigned gen = g_bar_gen;
        unsigned t = atomicAdd(&g_bar_count, 1u);
        if (t == NCTA - 1) {
            g_bar_count = 0;
            __threadfence();
            g_bar_gen = gen + 1;
        } else {
            while (g_bar_gen == gen) { }
            __threadfence();
        }
    }
    __syncthreads();
}

__global__ __launch_bounds__(NTHR) void lstm_persist(const float* __restrict__ X,
                                                     const float* __restrict__ Wh,
                                                     float* __restrict__ ys) {
    extern __shared__ uint32_t dsm[];
    uint32_t* ws  = dsm;                       // [1024][36] Wh slice (tf32)
    float*    hs  = (float*)(dsm + WS_WORDS);  // [3][64][68] h tiles (float)
    float*    gsm = (float*)(dsm + WS_WORDS + HS_WORDS); // [2][64][34] partials

    const int tid  = threadIdx.x;
    const int lane = tid & 31;
    const int w    = tid >> 5;        // warp 0..15
    const int lq   = lane >> 2;
    const int lr   = lane & 3;
    const int j    = blockIdx.x;      // hidden slice

    const int kh   = w >> 3;          // k-half within the 64-wide tile
    const int wm16 = ((w >> 1) & 3) * 16;  // M offset: 4 splits of 16 rows
    const int wn   = w & 1;           // N half: gates {0,1} or {2,3}
    const int joff = j & (NKT - 1);   // per-CTA k-order stagger

    // ---- preload Wh slice into SMEM once (converted to tf32) ----
    {
        const int rr = tid >> 3;
        const int q  = tid & 7;
        const int g  = q >> 1;
        const int half = q & 1;
        for (int base = 0; base < HDIM; base += 64) {
            float4 v = *(const float4*)(Wh + (size_t)(base + rr) * GDIM + g * HDIM + j * 8 + half * 4);
            st_tf32_4(ws + (base + rr) * WS_STR + q * 4, v);
        }
    }
    __syncthreads();

    // h staging map: 512 threads, row = tid>>3 (0..63), 8 floats (2 cpa16)
    const int hr = tid >> 3;
    const int hc = (tid & 7) * 8;

    // epilogue map: one output per thread
    const int er = tid >> 3;          // batch row 0..63
    const int eu = tid & 7;           // hidden unit 0..7

    for (int t = 0; t < T_STEPS; t++) {
        const int cur = t & 1;
        const int nxt = cur ^ 1;
        const float* hprev = g_h[cur];
        const float* cprev = g_c[cur];
        float* hnex = g_h[nxt];
        float* cnex = g_c[nxt];
        const float* gx = g_gates + (size_t)t * BATCH * GDIM;

        // ---- L2 prefetch of this step's epilogue gate operands ----
        {
            const float* gp = gx + (size_t)er * GDIM + j * 8 + eu;
            pfL2(gp);
            pfL2(gp + HDIM);
            pfL2(gp + 2 * HDIM);
            pfL2(gp + 3 * HDIM);
        }

        float acc[2][4];                       // [ni][frag], 2 gate cols of 8
#pragma unroll
        for (int ni = 0; ni < 2; ni++)
#pragma unroll
            for (int q = 0; q < 4; q++) acc[ni][q] = 0.0f;

        // ---- cp.async pipeline prologue: stages 0 and 1 (staggered order) --
#pragma unroll
        for (int s = 0; s < 2; s++) {
            const int kt = (s + joff) & (NKT - 1);
            float* hb = hs + s * (BATCH * HS_STR);
            cpa16(hb + hr * HS_STR + hc,     hprev + (size_t)hr * HDIM + kt * KTILE + hc);
            cpa16(hb + hr * HS_STR + hc + 4, hprev + (size_t)hr * HDIM + kt * KTILE + hc + 4);
            CP_COMMIT();
        }

        for (int it = 0; it < NKT; it++) {
            CP_WAIT1();
            __syncthreads();

            if (it + 2 < NKT) {
                const int kt2 = (it + 2 + joff) & (NKT - 1);
                float* hb2 = hs + ((it + 2) % NSTG) * (BATCH * HS_STR);
                cpa16(hb2 + hr * HS_STR + hc,     hprev + (size_t)hr * HDIM + kt2 * KTILE + hc);
                cpa16(hb2 + hr * HS_STR + hc + 4, hprev + (size_t)hr * HDIM + kt2 * KTILE + hc + 4);
            }
            CP_COMMIT();

            const float* hb = hs + (it % NSTG) * (BATCH * HS_STR);
            const int kt = (it + joff) & (NKT - 1);
            const int k0 = kt * KTILE;
#pragma unroll
            for (int ks = 0; ks < 4; ks++) {
                const int kk = kh * 32 + ks * 8;
                int r = wm16 + lq;
                uint32_t a0 = f2tf32(hb[r * HS_STR + kk + lr]);
                uint32_t a1 = f2tf32(hb[(r + 8) * HS_STR + kk + lr]);
                uint32_t a2 = f2tf32(hb[r * HS_STR + kk + lr + 4]);
                uint32_t a3 = f2tf32(hb[(r + 8) * HS_STR + kk + lr + 4]);
#pragma unroll
                for (int ni = 0; ni < 2; ni++) {
                    int g = wn * 2 + ni;       // gate 0..3
                    uint32_t b0 = ws[(k0 + kk + lr) * WS_STR + g * 8 + lq];
                    uint32_t b1 = ws[(k0 + kk + lr + 4) * WS_STR + g * 8 + lq];
                    mma_tf32(acc[ni], a0, a1, a2, a3, b0, b1);
                }
            }
        }

        // ---- exchange: dump warp partials to gsm[kh][64][34] ----
        {
            float* gs = gsm + kh * (BATCH * GS_STR);
#pragma unroll
            for (int ni = 0; ni < 2; ni++) {
                int col = (wn * 2 + ni) * 8 + 2 * lr;
                int row = wm16 + lq;
                gs[row * GS_STR + col]           = acc[ni][0];
                gs[row * GS_STR + col + 1]       = acc[ni][1];
                gs[(row + 8) * GS_STR + col]     = acc[ni][2];
                gs[(row + 8) * GS_STR + col + 1] = acc[ni][3];
            }
        }
        __syncthreads();

        // ---- cell epilogue: one output per thread (512 outputs) ----
        {
            const int r = er, u = eu;
            const int hcol = j * 8 + u;
            const float* g0 = gsm + r * GS_STR;
            const float* g1 = gsm + BATCH * GS_STR + r * GS_STR;

            bool m = (__ldcg(&g_eos[cur][r]) != 0);
            const float* gp = gx + (size_t)r * GDIM + hcol;
            float iv = g0[u]      + g1[u]      + __ldg(gp);
            float fv = g0[8 + u]  + g1[8 + u]  + __ldg(gp + HDIM);
            float gv = g0[16 + u] + g1[16 + u] + __ldg(gp + 2 * HDIM);
            float ov = g0[24 + u] + g1[24 + u] + __ldg(gp + 3 * HDIM);

            float cp  = __ldcg(cprev + (size_t)r * HDIM + hcol);
            float ncv = sigf(fv) * cp + sigf(iv) * tanhf(gv);
            float nhv = sigf(ov) * tanhf(ncv);

            ys[((size_t)t * BATCH + r) * HDIM + hcol] = nhv;   // unmasked
            cnex[(size_t)r * HDIM + hcol] = m ? cp : ncv;
            hnex[(size_t)r * HDIM + hcol] = m ? __ldcg(hprev + (size_t)r * HDIM + hcol) : nhv;
        }

        if (blockIdx.x == 0 && tid < BATCH) {
            float xe = __ldg(X + ((size_t)t * BATCH + tid) * VDIM + 1);
            int eo = __ldcg(&g_eos[cur][tid]);
            g_eos[nxt][tid] = (eo != 0 || xe != 0.0f) ? 1 : 0;
        }

        __threadfence();
        grid_barrier();   // also protects gsm + hs reuse next step
    }
}

// ---------------- launch ---------------------------------------------------
extern "C" void kernel_launch(void* const* d_in, const int* in_sizes, int n_in,
                              void* d_out, int out_size) {
    const float* x  = (const float*)d_in[0];
    const float* Wi = (const float*)d_in[1];
    const float* Wh = (const float*)d_in[2];
    const float* b  = (const float*)d_in[3];
    const float* c0 = (const float*)d_in[4];
    const float* h0 = (const float*)d_in[5];
    const unsigned char* eos0 = (const unsigned char*)d_in[6];
    float* ys = (float*)d_out;

    static bool attr_done = false;
    if (!attr_done) {
        cudaFuncSetAttribute(lstm_persist,
                             cudaFuncAttributeMaxDynamicSharedMemorySize, PSMEM_BYTES);
        attr_done = true;
    }

    init_state<<<(BATCH * HDIM + 255) / 256, 256>>>(c0, h0, eos0);

    dim3 g1(GDIM / G1_BN, (T_STEPS * BATCH) / G1_BM);   // 32 x 64
    gemm1<<<g1, 256>>>(x, Wi, b);

    lstm_persist<<<NCTA, NTHR, PSMEM_BYTES>>>(x, Wh, ys);
}

// round 15
// speedup vs baseline: 2.5988x; 1.0893x over previous
#include <cuda_runtime.h>
#include <cstdint>

#define T_STEPS 128
#define BATCH   64
#define VDIM    2048
#define HDIM    1024
#define GDIM    4096   // 4*H

#define NCTA    128    // persistent CTAs (one per 8 hidden units)
#define NTHR    512    // 16 warps: 4 (M) x 2 (N/gate-pair) x 2 (K-split)

// ---------------- scratch (static device globals; no allocation) ----------
__device__ float g_gates[(size_t)T_STEPS * BATCH * GDIM];  // 134 MB: x@Wi + b
__device__ float g_h[2][BATCH * HDIM];
__device__ float g_c[2][BATCH * HDIM];
__device__ int   g_eos[2][BATCH];
__device__ unsigned g_bar_count;
__device__ volatile unsigned g_bar_gen;

// ---------------- helpers ------------------------------------------------
__device__ __forceinline__ uint32_t f2tf32(float f) {
    uint32_t r;
    asm("cvt.rna.tf32.f32 %0, %1;" : "=r"(r) : "f"(f));
    return r;
}

__device__ __forceinline__ void st_tf32_4(uint32_t* d, float4 v) {
    uint4 u;
    u.x = f2tf32(v.x); u.y = f2tf32(v.y); u.z = f2tf32(v.z); u.w = f2tf32(v.w);
    *(uint4*)d = u;
}

__device__ __forceinline__ void mma_tf32(float c[4],
                                         uint32_t a0, uint32_t a1, uint32_t a2, uint32_t a3,
                                         uint32_t b0, uint32_t b1) {
    asm volatile(
        "mma.sync.aligned.m16n8k8.row.col.f32.tf32.tf32.f32 "
        "{%0,%1,%2,%3}, {%4,%5,%6,%7}, {%8,%9}, {%0,%1,%2,%3};\n"
        : "+f"(c[0]), "+f"(c[1]), "+f"(c[2]), "+f"(c[3])
        : "r"(a0), "r"(a1), "r"(a2), "r"(a3), "r"(b0), "r"(b1));
}

__device__ __forceinline__ float sigf(float x) {
    return 1.0f / (1.0f + expf(-x));
}

__device__ __forceinline__ void cpa16(void* dst_smem, const void* src_glob) {
    uint32_t d = (uint32_t)__cvta_generic_to_shared(dst_smem);
    asm volatile("cp.async.cg.shared.global [%0], [%1], 16;\n" :: "r"(d), "l"(src_glob));
}
#define CP_COMMIT() asm volatile("cp.async.commit_group;\n" ::: "memory")
#define CP_WAIT1()  asm volatile("cp.async.wait_group 1;\n" ::: "memory")
#define CP_WAIT2()  asm volatile("cp.async.wait_group 2;\n" ::: "memory")

__device__ __forceinline__ void pfL2(const void* p) {
    asm volatile("prefetch.global.L2 [%0];\n" :: "l"(p));
}

// ---------------- init state ---------------------------------------------
__global__ void init_state(const float* __restrict__ c0,
                           const float* __restrict__ h0,
                           const unsigned char* __restrict__ eos0) {
    int i = blockIdx.x * blockDim.x + threadIdx.x;
    if (i < BATCH * HDIM) {
        g_c[0][i] = c0[i];
        g_h[0][i] = h0[i];
    }
    if (i < BATCH) g_eos[0][i] = eos0[i] ? 1 : 0;
    if (i == 0) { g_bar_count = 0; g_bar_gen = 0; }
}

// ---------------- phase 1: gates_x = X @ Wi + b  (round-4/10 proven) -------
#define G1_BM 128
#define G1_BN 128
#define G1_BK 16
#define G1_ASTR 20
#define G1_BSTR 132

__global__ __launch_bounds__(256) void gemm1(const float* __restrict__ X,
                                             const float* __restrict__ Wi,
                                             const float* __restrict__ bias) {
    __shared__ uint32_t As[2][G1_BM * G1_ASTR];
    __shared__ uint32_t Bs[2][G1_BK * G1_BSTR];

    const int tid  = threadIdx.x;
    const int lane = tid & 31;
    const int wid  = tid >> 5;
    const int wm   = (wid >> 1) * 32;
    const int wn   = (wid & 1) * 64;
    const int lq   = lane >> 2;
    const int lr   = lane & 3;

    const int m0 = blockIdx.y * G1_BM;
    const int n0 = blockIdx.x * G1_BN;

    float acc[2][8][4];
#pragma unroll
    for (int mi = 0; mi < 2; mi++)
#pragma unroll
        for (int ni = 0; ni < 8; ni++)
#pragma unroll
            for (int q = 0; q < 4; q++) acc[mi][ni][q] = 0.0f;

    const int ar = tid >> 1;
    const int ac = (tid & 1) * 8;
    const int br = tid >> 4;
    const int bc = (tid & 15) * 8;

    const float* asrc = X  + (size_t)(m0 + ar) * VDIM + ac;
    const float* bsrc = Wi + (size_t)br * GDIM + n0 + bc;

    float4 av0 = *(const float4*)(asrc);
    float4 av1 = *(const float4*)(asrc + 4);
    float4 bv0 = *(const float4*)(bsrc);
    float4 bv1 = *(const float4*)(bsrc + 4);

    const int NIT = VDIM / G1_BK;   // 128
    for (int it = 0; it < NIT; it++) {
        const int p = it & 1;
        st_tf32_4(&As[p][ar * G1_ASTR + ac],     av0);
        st_tf32_4(&As[p][ar * G1_ASTR + ac + 4], av1);
        st_tf32_4(&Bs[p][br * G1_BSTR + bc],     bv0);
        st_tf32_4(&Bs[p][br * G1_BSTR + bc + 4], bv1);
        __syncthreads();

        if (it + 1 < NIT) {
            int k1 = (it + 1) * G1_BK;
            av0 = *(const float4*)(asrc + k1);
            av1 = *(const float4*)(asrc + k1 + 4);
            bv0 = *(const float4*)(bsrc + (size_t)k1 * GDIM);
            bv1 = *(const float4*)(bsrc + (size_t)k1 * GDIM + 4);
        }

        const uint32_t* as = As[p];
        const uint32_t* bs = Bs[p];
#pragma unroll
        for (int kk = 0; kk < G1_BK; kk += 8) {
            uint32_t afr[2][4];
#pragma unroll
            for (int mi = 0; mi < 2; mi++) {
                int r = wm + mi * 16 + lq;
                afr[mi][0] = as[r * G1_ASTR + kk + lr];
                afr[mi][1] = as[(r + 8) * G1_ASTR + kk + lr];
                afr[mi][2] = as[r * G1_ASTR + kk + lr + 4];
                afr[mi][3] = as[(r + 8) * G1_ASTR + kk + lr + 4];
            }
            uint32_t bfr[8][2];
#pragma unroll
            for (int ni = 0; ni < 8; ni++) {
                int c = wn + ni * 8 + lq;
                bfr[ni][0] = bs[(kk + lr) * G1_BSTR + c];
                bfr[ni][1] = bs[(kk + lr + 4) * G1_BSTR + c];
            }
#pragma unroll
            for (int mi = 0; mi < 2; mi++)
#pragma unroll
                for (int ni = 0; ni < 8; ni++)
                    mma_tf32(acc[mi][ni], afr[mi][0], afr[mi][1], afr[mi][2], afr[mi][3],
                             bfr[ni][0], bfr[ni][1]);
        }
    }

#pragma unroll
    for (int mi = 0; mi < 2; mi++) {
#pragma unroll
        for (int ni = 0; ni < 8; ni++) {
            int r0 = m0 + wm + mi * 16 + lq;
            int c0 = n0 + wn + ni * 8 + 2 * lr;
            float bl = bias[c0];
            float bh = bias[c0 + 1];
            g_gates[(size_t)r0 * GDIM + c0]           = acc[mi][ni][0] + bl;
            g_gates[(size_t)r0 * GDIM + c0 + 1]       = acc[mi][ni][1] + bh;
            g_gates[(size_t)(r0 + 8) * GDIM + c0]     = acc[mi][ni][2] + bl;
            g_gates[(size_t)(r0 + 8) * GDIM + c0 + 1] = acc[mi][ni][3] + bh;
        }
    }
}

// ---------------- phase 2: persistent recurrent kernel ---------------------
// R10 logic; changes: 4-stage cp.async pipeline (prefetch distance 3,
// wait_group 2) and removal of the redundant all-thread threadfence before
// the grid barrier (barrier's internal release pattern suffices).
#define NSTG 4
#define WS_STR 36
#define HS_STR 36
#define GS_STR 34
#define WS_WORDS (HDIM * WS_STR)                // 36864
#define HS_WORDS (NSTG * BATCH * HS_STR)        // 9216
#define GS_WORDS (2 * BATCH * GS_STR)           // 4352
#define PSMEM_BYTES ((WS_WORDS + HS_WORDS + GS_WORDS) * 4) // 201728 B

__device__ __forceinline__ void grid_barrier() {
    __syncthreads();
    if (threadIdx.x == 0) {
        __threadfence();   // release: all block stores (ordered via bar) -> global
        unsigned gen = g_bar_gen;
        unsigned t = atomicAdd(&g_bar_count, 1u);
        if (t == NCTA - 1) {
            g_bar_count = 0;
            __threadfence();
            g_bar_gen = gen + 1;
        } else {
            while (g_bar_gen == gen) { }
            __threadfence(); // acquire
        }
    }
    __syncthreads();
}

__global__ __launch_bounds__(NTHR) void lstm_persist(const float* __restrict__ X,
                                                     const float* __restrict__ Wh,
                                                     float* __restrict__ ys) {
    extern __shared__ uint32_t dsm[];
    uint32_t* ws  = dsm;                       // [1024][36] Wh slice (tf32)
    float*    hs  = (float*)(dsm + WS_WORDS);  // [4][64][36] h tiles (float)
    float*    gsm = (float*)(dsm + WS_WORDS + HS_WORDS); // [2][64][34] partials

    const int tid  = threadIdx.x;
    const int lane = tid & 31;
    const int w    = tid >> 5;        // warp 0..15
    const int lq   = lane >> 2;
    const int lr   = lane & 3;
    const int j    = blockIdx.x;      // hidden slice

    const int kh   = w >> 3;          // k-half: kk in {0,8} or {16,24}
    const int wm16 = ((w >> 1) & 3) * 16;  // M offset: 4 splits of 16 rows
    const int wn   = w & 1;           // N half: gates {0,1} or {2,3}

    // ---- preload Wh slice into SMEM once (converted to tf32) ----
    {
        const int rr = tid >> 3;
        const int q  = tid & 7;
        const int g  = q >> 1;
        const int half = q & 1;
        for (int base = 0; base < HDIM; base += 64) {
            float4 v = *(const float4*)(Wh + (size_t)(base + rr) * GDIM + g * HDIM + j * 8 + half * 4);
            st_tf32_4(ws + (base + rr) * WS_STR + q * 4, v);
        }
    }
    __syncthreads();

    // h staging map: 512 threads, row = tid>>3 (0..63), 4 floats each
    const int hr = tid >> 3;
    const int hc = (tid & 7) * 4;
    const int NIT = HDIM / 32;        // 32 k-tiles per step

    // epilogue map: one output per thread
    const int er = tid >> 3;          // batch row 0..63
    const int eu = tid & 7;           // hidden unit 0..7

    for (int t = 0; t < T_STEPS; t++) {
        const int cur = t & 1;
        const int nxt = cur ^ 1;
        const float* hprev = g_h[cur];
        const float* cprev = g_c[cur];
        float* hnex = g_h[nxt];
        float* cnex = g_c[nxt];
        const float* gx = g_gates + (size_t)t * BATCH * GDIM;

        // ---- L2 prefetch of this step's epilogue gate operands ----
        {
            const float* gp = gx + (size_t)er * GDIM + j * 8 + eu;
            pfL2(gp);
            pfL2(gp + HDIM);
            pfL2(gp + 2 * HDIM);
            pfL2(gp + 3 * HDIM);
        }

        float acc[2][4];                       // [ni][frag], 2 gate cols of 8
#pragma unroll
        for (int ni = 0; ni < 2; ni++)
#pragma unroll
            for (int q = 0; q < 4; q++) acc[ni][q] = 0.0f;

        // ---- cp.async pipeline prologue: stages 0,1,2 ----
#pragma unroll
        for (int s = 0; s < 3; s++) {
            float* hb = hs + s * (BATCH * HS_STR);
            cpa16(hb + hr * HS_STR + hc, hprev + (size_t)hr * HDIM + s * 32 + hc);
            CP_COMMIT();
        }

        for (int it = 0; it < NIT; it++) {
            CP_WAIT2();          // oldest of 3 pending groups (tile it) done
            __syncthreads();

            if (it + 3 < NIT) {
                float* hb2 = hs + ((it + 3) % NSTG) * (BATCH * HS_STR);
                cpa16(hb2 + hr * HS_STR + hc, hprev + (size_t)hr * HDIM + (it + 3) * 32 + hc);
            }
            CP_COMMIT();

            const float* hb = hs + (it % NSTG) * (BATCH * HS_STR);
            const int k0 = it * 32;
#pragma unroll
            for (int ks = 0; ks < 2; ks++) {
                const int kk = kh * 16 + ks * 8;
                int r = wm16 + lq;
                uint32_t a0 = f2tf32(hb[r * HS_STR + kk + lr]);
                uint32_t a1 = f2tf32(hb[(r + 8) * HS_STR + kk + lr]);
                uint32_t a2 = f2tf32(hb[r * HS_STR + kk + lr + 4]);
                uint32_t a3 = f2tf32(hb[(r + 8) * HS_STR + kk + lr + 4]);
#pragma unroll
                for (int ni = 0; ni < 2; ni++) {
                    int g = wn * 2 + ni;       // gate 0..3
                    uint32_t b0 = ws[(k0 + kk + lr) * WS_STR + g * 8 + lq];
                    uint32_t b1 = ws[(k0 + kk + lr + 4) * WS_STR + g * 8 + lq];
                    mma_tf32(acc[ni], a0, a1, a2, a3, b0, b1);
                }
            }
        }

        // ---- exchange: dump warp partials to gsm[kh][64][34] ----
        {
            float* gs = gsm + kh * (BATCH * GS_STR);
#pragma unroll
            for (int ni = 0; ni < 2; ni++) {
                int col = (wn * 2 + ni) * 8 + 2 * lr;
                int row = wm16 + lq;
                gs[row * GS_STR + col]           = acc[ni][0];
                gs[row * GS_STR + col + 1]       = acc[ni][1];
                gs[(row + 8) * GS_STR + col]     = acc[ni][2];
                gs[(row + 8) * GS_STR + col + 1] = acc[ni][3];
            }
        }
        __syncthreads();

        // ---- cell epilogue: one output per thread (512 outputs) ----
        {
            const int r = er, u = eu;
            const int hcol = j * 8 + u;
            const float* g0 = gsm + r * GS_STR;
            const float* g1 = gsm + BATCH * GS_STR + r * GS_STR;

            bool m = (__ldcg(&g_eos[cur][r]) != 0);
            const float* gp = gx + (size_t)r * GDIM + hcol;
            float iv = g0[u]      + g1[u]      + __ldg(gp);
            float fv = g0[8 + u]  + g1[8 + u]  + __ldg(gp + HDIM);
            float gv = g0[16 + u] + g1[16 + u] + __ldg(gp + 2 * HDIM);
            float ov = g0[24 + u] + g1[24 + u] + __ldg(gp + 3 * HDIM);

            float cp  = __ldcg(cprev + (size_t)r * HDIM + hcol);
            float ncv = sigf(fv) * cp + sigf(iv) * tanhf(gv);
            float nhv = sigf(ov) * tanhf(ncv);

            ys[((size_t)t * BATCH + r) * HDIM + hcol] = nhv;   // unmasked
            cnex[(size_t)r * HDIM + hcol] = m ? cp : ncv;
            hnex[(size_t)r * HDIM + hcol] = m ? __ldcg(hprev + (size_t)r * HDIM + hcol) : nhv;
        }

        if (blockIdx.x == 0 && tid < BATCH) {
            float xe = __ldg(X + ((size_t)t * BATCH + tid) * VDIM + 1);
            int eo = __ldcg(&g_eos[cur][tid]);
            g_eos[nxt][tid] = (eo != 0 || xe != 0.0f) ? 1 : 0;
        }

        grid_barrier();   // release via internal sync+fence; protects gsm/hs reuse
    }
}

// ---------------- launch ---------------------------------------------------
extern "C" void kernel_launch(void* const* d_in, const int* in_sizes, int n_in,
                              void* d_out, int out_size) {
    const float* x  = (const float*)d_in[0];
    const float* Wi = (const float*)d_in[1];
    const float* Wh = (const float*)d_in[2];
    const float* b  = (const float*)d_in[3];
    const float* c0 = (const float*)d_in[4];
    const float* h0 = (const float*)d_in[5];
    const unsigned char* eos0 = (const unsigned char*)d_in[6];
    float* ys = (float*)d_out;

    static bool attr_done = false;
    if (!attr_done) {
        cudaFuncSetAttribute(lstm_persist,
                             cudaFuncAttributeMaxDynamicSharedMemorySize, PSMEM_BYTES);
        attr_done = true;
    }

    init_state<<<(BATCH * HDIM + 255) / 256, 256>>>(c0, h0, eos0);

    dim3 g1(GDIM / G1_BN, (T_STEPS * BATCH) / G1_BM);   // 32 x 64
    gemm1<<<g1, 256>>>(x, Wi, b);

    lstm_persist<<<NCTA, NTHR, PSMEM_BYTES>>>(x, Wh, ys);
}